// round 9
// baseline (speedup 1.0000x reference)
#include <cuda_runtime.h>
#include <cuda_fp16.h>

#define DIM 160
#define N_VOX (DIM * DIM * DIM)

// fp32 carried field, SoA planes (ping-pong)
__device__ float g_vxA[N_VOX], g_vyA[N_VOX], g_vzA[N_VOX];
__device__ float g_vxB[N_VOX], g_vyB[N_VOX], g_vzB[N_VOX];
// fp16x4 mirror (8B/voxel) — gather source only
__device__ __align__(16) uint2 g_h16A[N_VOX];
__device__ __align__(16) uint2 g_h16B[N_VOX];

__device__ __forceinline__ uint2 pack_h16(float x, float y, float z)
{
    __half2 hxy = __floats2half2_rn(x, y);
    __half2 hz  = __floats2half2_rn(z, 0.0f);
    uint2 r;
    r.x = *reinterpret_cast<unsigned int*>(&hxy);
    r.y = *reinterpret_cast<unsigned int*>(&hz);
    return r;
}

__device__ __forceinline__ __half2 as_h2(unsigned u)
{
    return *reinterpret_cast<__half2*>(&u);
}

// One squaring step: vout = v + trilinear_sample(v, identity + v).
// FIRST: own voxel from vel (AoS 12B) with 2^-6 prescale fused.
// Gather: 8x LDG.64 fp16 mirror; x-pair combine in packed half2, y/z in fp32.
// Bounds: warp-uniform vote — interior warps skip all clamp/mask work.
template <bool FIRST, bool LAST>
__global__ void __launch_bounds__(160, 12)
step_kernel(const float* __restrict__ vx32, const float* __restrict__ vy32,
            const float* __restrict__ vz32, const uint2* __restrict__ vin16,
            float* __restrict__ oxp, float* __restrict__ oyp,
            float* __restrict__ ozp, uint2* __restrict__ vout16,
            float* __restrict__ out_packed)
{
    __shared__ float sflat[3 * DIM];

    int ix = threadIdx.x;
    int iy = blockIdx.x;
    int iz = blockIdx.y;
    int idx = (iz * DIM + iy) * DIM + ix;

    float vx, vy, vz;
    if (FIRST) {
        const float s = 1.0f / 64.0f;
        vx = __ldg(vx32 + 3 * idx + 0) * s;
        vy = __ldg(vx32 + 3 * idx + 1) * s;
        vz = __ldg(vx32 + 3 * idx + 2) * s;
    } else {
        vx = vx32[idx];
        vy = vy32[idx];
        vz = vz32[idx];
    }

    const float half = 0.5f * (float)(DIM - 1);  // 79.5
    float x = (float)ix + half * vx;
    float y = (float)iy + half * vy;
    float z = (float)iz + half * vz;

    float xf = floorf(x), yf = floorf(y), zf = floorf(z);
    int x0 = (int)xf, y0 = (int)yf, z0 = (int)zf;
    float fx = x - xf, fy = y - yf, fz = z - zf;

    int x0c, x1c, y0c, y1c, z0c, z1c;
    float wx0, wx1, wy0, wy1, wz0, wz1;

    // Interior iff all of x0,y0,z0 in [0, DIM-2] (then x0+1 <= DIM-1 too).
    bool interior = ((unsigned)x0 <= (unsigned)(DIM - 2)) &
                    ((unsigned)y0 <= (unsigned)(DIM - 2)) &
                    ((unsigned)z0 <= (unsigned)(DIM - 2));

    if (__all_sync(0xffffffffu, interior)) {
        // Fast path: raw indices, unmasked weights.
        x0c = x0; x1c = x0 + 1;
        y0c = y0; y1c = y0 + 1;
        z0c = z0; z1c = z0 + 1;
        wx0 = 1.0f - fx; wx1 = fx;
        wy0 = 1.0f - fy; wy1 = fy;
        wz0 = 1.0f - fz; wz1 = fz;
    } else {
        // Exact zeros-padding path: clamp + masked weights.
        x0c = min(max(x0, 0), DIM - 1);
        x1c = min(max(x0 + 1, 0), DIM - 1);
        y0c = min(max(y0, 0), DIM - 1);
        y1c = min(max(y0 + 1, 0), DIM - 1);
        z0c = min(max(z0, 0), DIM - 1);
        z1c = min(max(z0 + 1, 0), DIM - 1);
        wx0 = ((unsigned)x0       < (unsigned)DIM) ? (1.0f - fx) : 0.0f;
        wx1 = ((unsigned)(x0 + 1) < (unsigned)DIM) ? fx          : 0.0f;
        wy0 = ((unsigned)y0       < (unsigned)DIM) ? (1.0f - fy) : 0.0f;
        wy1 = ((unsigned)(y0 + 1) < (unsigned)DIM) ? fy          : 0.0f;
        wz0 = ((unsigned)z0       < (unsigned)DIM) ? (1.0f - fz) : 0.0f;
        wz1 = ((unsigned)(z0 + 1) < (unsigned)DIM) ? fz          : 0.0f;
    }

    int rb00 = (z0c * DIM + y0c) * DIM;
    int rb01 = (z0c * DIM + y1c) * DIM;
    int rb10 = (z1c * DIM + y0c) * DIM;
    int rb11 = (z1c * DIM + y1c) * DIM;
    float w00 = wz0 * wy0, w01 = wz0 * wy1, w10 = wz1 * wy0, w11 = wz1 * wy1;

    // Issue all 8 gathers up front (MLP).
    uint2 q0 = __ldg(vin16 + rb00 + x0c);
    uint2 q1 = __ldg(vin16 + rb00 + x1c);
    uint2 q2 = __ldg(vin16 + rb01 + x0c);
    uint2 q3 = __ldg(vin16 + rb01 + x1c);
    uint2 q4 = __ldg(vin16 + rb10 + x0c);
    uint2 q5 = __ldg(vin16 + rb10 + x1c);
    uint2 q6 = __ldg(vin16 + rb11 + x0c);
    uint2 q7 = __ldg(vin16 + rb11 + x1c);

    // x-pair combine in packed fp16, y/z combine in fp32.
    __half2 wl2 = __float2half2_rn(wx0);
    __half2 wh2 = __float2half2_rn(wx1);

    float ax = 0.0f, ay = 0.0f, az = 0.0f;
#pragma unroll
    for (int r = 0; r < 4; r++) {
        uint2 qlo, qhi;
        float wyz;
        switch (r) {
            case 0:  qlo = q0; qhi = q1; wyz = w00; break;
            case 1:  qlo = q2; qhi = q3; wyz = w01; break;
            case 2:  qlo = q4; qhi = q5; wyz = w10; break;
            default: qlo = q6; qhi = q7; wyz = w11; break;
        }
        __half2 rxy = __hfma2(wh2, as_h2(qhi.x), __hmul2(wl2, as_h2(qlo.x)));
        __half2 rz_ = __hfma2(wh2, as_h2(qhi.y), __hmul2(wl2, as_h2(qlo.y)));
        float2 fxy = __half22float2(rxy);
        ax = fmaf(wyz, fxy.x, ax);
        ay = fmaf(wyz, fxy.y, ay);
        az = fmaf(wyz, __low2float(rz_), az);
    }

    float ox = vx + ax, oy = vy + ay, oz = vz + az;

    if (LAST) {
        sflat[3 * ix + 0] = ox;
        sflat[3 * ix + 1] = oy;
        sflat[3 * ix + 2] = oz;
        __syncthreads();
        float* o = out_packed + 3 * (idx - ix);
#pragma unroll
        for (int j = 0; j < 3; j++)
            o[ix + j * DIM] = sflat[ix + j * DIM];
    } else {
        oxp[idx] = ox;
        oyp[idx] = oy;
        ozp[idx] = oz;
        vout16[idx] = pack_h16(ox, oy, oz);
    }
}

// Slim repack: vel (packed 12B) -> fp16 mirror only (prescaled by 2^-6).
__global__ void __launch_bounds__(160)
mirror_kernel(const float* __restrict__ vel, uint2* __restrict__ m16)
{
    int ix = threadIdx.x;
    int iy = blockIdx.x;
    int iz = blockIdx.y;
    int idx = (iz * DIM + iy) * DIM + ix;
    int b = idx * 3;
    const float s = 1.0f / 64.0f;
    m16[idx] = pack_h16(vel[b] * s, vel[b + 1] * s, vel[b + 2] * s);
}

extern "C" void kernel_launch(void* const* d_in, const int* in_sizes, int n_in,
                              void* d_out, int out_size)
{
    const float* vel = (const float*)d_in[0];  // [1,160,160,160,3] f32
    // d_in[1] = identity grid (analytic). d_in[2] = n (= 6).
    float* out = (float*)d_out;

    float *vxA, *vyA, *vzA, *vxB, *vyB, *vzB;
    uint2 *hA, *hB;
    cudaGetSymbolAddress((void**)&vxA, g_vxA);
    cudaGetSymbolAddress((void**)&vyA, g_vyA);
    cudaGetSymbolAddress((void**)&vzA, g_vzA);
    cudaGetSymbolAddress((void**)&vxB, g_vxB);
    cudaGetSymbolAddress((void**)&vyB, g_vyB);
    cudaGetSymbolAddress((void**)&vzB, g_vzB);
    cudaGetSymbolAddress((void**)&hA, g_h16A);
    cudaGetSymbolAddress((void**)&hB, g_h16B);

    dim3 grid(DIM, DIM);
    dim3 block(DIM);

    mirror_kernel<<<grid, block>>>(vel, hA);

    step_kernel<true,  false><<<grid, block>>>(vel, nullptr, nullptr, hA,
                                               vxB, vyB, vzB, hB, nullptr);
    step_kernel<false, false><<<grid, block>>>(vxB, vyB, vzB, hB,
                                               vxA, vyA, vzA, hA, nullptr);
    step_kernel<false, false><<<grid, block>>>(vxA, vyA, vzA, hA,
                                               vxB, vyB, vzB, hB, nullptr);
    step_kernel<false, false><<<grid, block>>>(vxB, vyB, vzB, hB,
                                               vxA, vyA, vzA, hA, nullptr);
    step_kernel<false, false><<<grid, block>>>(vxA, vyA, vzA, hA,
                                               vxB, vyB, vzB, hB, nullptr);
    step_kernel<false, true ><<<grid, block>>>(vxB, vyB, vzB, hB,
                                               nullptr, nullptr, nullptr, nullptr, out);
}

// round 10
// speedup vs baseline: 1.2110x; 1.2110x over previous
#include <cuda_runtime.h>
#include <cuda_fp16.h>

#define DIM 160
#define N_VOX (DIM * DIM * DIM)

// Carried field = fp16x4 (8B/voxel), ping-pong. Gather source AND own-voxel.
__device__ __align__(16) uint2 g_h16A[N_VOX];
__device__ __align__(16) uint2 g_h16B[N_VOX];
// fp32 SoA copy written only by the penultimate step, read by the last step
// (keeps the final output's own-v term at full precision).
__device__ float g_vx[N_VOX], g_vy[N_VOX], g_vz[N_VOX];

__device__ __forceinline__ uint2 pack_h16(float x, float y, float z)
{
    __half2 hxy = __floats2half2_rn(x, y);
    __half2 hz  = __floats2half2_rn(z, 0.0f);
    uint2 r;
    r.x = *reinterpret_cast<unsigned int*>(&hxy);
    r.y = *reinterpret_cast<unsigned int*>(&hz);
    return r;
}

__device__ __forceinline__ __half2 as_h2(unsigned u)
{
    return *reinterpret_cast<__half2*>(&u);
}

// MODE: 0 = FIRST  (own from vel fp32 AoS, prescale fused; write h16)
//       1 = MIDDLE (own from h16; write h16)
//       2 = PENULT (own from h16; write h16 + fp32 SoA)
//       3 = LAST   (own from fp32 SoA; gather h16; write packed fp32 out)
template <int MODE>
__global__ void __launch_bounds__(160, 12)
step_kernel(const float* __restrict__ vel,
            const uint2* __restrict__ vin16,
            uint2* __restrict__ vout16,
            float* __restrict__ sx, float* __restrict__ sy,
            float* __restrict__ sz,
            float* __restrict__ out_packed)
{
    __shared__ float sflat[3 * DIM];

    int ix = threadIdx.x;
    int iy = blockIdx.x;
    int iz = blockIdx.y;
    int idx = (iz * DIM + iy) * DIM + ix;

    float vx, vy, vz;
    if (MODE == 0) {
        const float s = 1.0f / 64.0f;
        vx = __ldg(vel + 3 * idx + 0) * s;
        vy = __ldg(vel + 3 * idx + 1) * s;
        vz = __ldg(vel + 3 * idx + 2) * s;
    } else if (MODE == 3) {
        vx = sx[idx];
        vy = sy[idx];
        vz = sz[idx];
    } else {
        uint2 q = vin16[idx];
        float2 xy = __half22float2(as_h2(q.x));
        float2 z2 = __half22float2(as_h2(q.y));
        vx = xy.x; vy = xy.y; vz = z2.x;
    }

    const float half = 0.5f * (float)(DIM - 1);  // 79.5
    float x = (float)ix + half * vx;
    float y = (float)iy + half * vy;
    float z = (float)iz + half * vz;

    float xf = floorf(x), yf = floorf(y), zf = floorf(z);
    int x0 = (int)xf, y0 = (int)yf, z0 = (int)zf;
    float fx = x - xf, fy = y - yf, fz = z - zf;

    int x0c = min(max(x0, 0), DIM - 1);
    int x1c = min(max(x0 + 1, 0), DIM - 1);
    int y0c = min(max(y0, 0), DIM - 1);
    int y1c = min(max(y0 + 1, 0), DIM - 1);
    int z0c = min(max(z0, 0), DIM - 1);
    int z1c = min(max(z0 + 1, 0), DIM - 1);
    float wx0 = ((unsigned)x0       < (unsigned)DIM) ? (1.0f - fx) : 0.0f;
    float wx1 = ((unsigned)(x0 + 1) < (unsigned)DIM) ? fx          : 0.0f;
    float wy0 = ((unsigned)y0       < (unsigned)DIM) ? (1.0f - fy) : 0.0f;
    float wy1 = ((unsigned)(y0 + 1) < (unsigned)DIM) ? fy          : 0.0f;
    float wz0 = ((unsigned)z0       < (unsigned)DIM) ? (1.0f - fz) : 0.0f;
    float wz1 = ((unsigned)(z0 + 1) < (unsigned)DIM) ? fz          : 0.0f;

    int rb00 = (z0c * DIM + y0c) * DIM;
    int rb01 = (z0c * DIM + y1c) * DIM;
    int rb10 = (z1c * DIM + y0c) * DIM;
    int rb11 = (z1c * DIM + y1c) * DIM;
    float w00 = wz0 * wy0, w01 = wz0 * wy1, w10 = wz1 * wy0, w11 = wz1 * wy1;

    // Issue all 8 gathers up front (MLP).
    uint2 q0 = __ldg(vin16 + rb00 + x0c);
    uint2 q1 = __ldg(vin16 + rb00 + x1c);
    uint2 q2 = __ldg(vin16 + rb01 + x0c);
    uint2 q3 = __ldg(vin16 + rb01 + x1c);
    uint2 q4 = __ldg(vin16 + rb10 + x0c);
    uint2 q5 = __ldg(vin16 + rb10 + x1c);
    uint2 q6 = __ldg(vin16 + rb11 + x0c);
    uint2 q7 = __ldg(vin16 + rb11 + x1c);

    // x-pair combine in packed fp16, y/z combine in fp32.
    __half2 wl2 = __float2half2_rn(wx0);
    __half2 wh2 = __float2half2_rn(wx1);

    float ax = 0.0f, ay = 0.0f, az = 0.0f;
#pragma unroll
    for (int r = 0; r < 4; r++) {
        uint2 qlo, qhi;
        float wyz;
        switch (r) {
            case 0:  qlo = q0; qhi = q1; wyz = w00; break;
            case 1:  qlo = q2; qhi = q3; wyz = w01; break;
            case 2:  qlo = q4; qhi = q5; wyz = w10; break;
            default: qlo = q6; qhi = q7; wyz = w11; break;
        }
        __half2 rxy = __hfma2(wh2, as_h2(qhi.x), __hmul2(wl2, as_h2(qlo.x)));
        __half2 rz_ = __hfma2(wh2, as_h2(qhi.y), __hmul2(wl2, as_h2(qlo.y)));
        float2 fxy = __half22float2(rxy);
        ax = fmaf(wyz, fxy.x, ax);
        ay = fmaf(wyz, fxy.y, ay);
        az = fmaf(wyz, __low2float(rz_), az);
    }

    float ox = vx + ax, oy = vy + ay, oz = vz + az;

    if (MODE == 3) {
        sflat[3 * ix + 0] = ox;
        sflat[3 * ix + 1] = oy;
        sflat[3 * ix + 2] = oz;
        __syncthreads();
        float* o = out_packed + 3 * (idx - ix);
#pragma unroll
        for (int j = 0; j < 3; j++)
            o[ix + j * DIM] = sflat[ix + j * DIM];
    } else {
        vout16[idx] = pack_h16(ox, oy, oz);
        if (MODE == 2) {
            sx[idx] = ox;
            sy[idx] = oy;
            sz[idx] = oz;
        }
    }
}

// Build gather mirror of the prescaled velocity.
__global__ void __launch_bounds__(160)
mirror_kernel(const float* __restrict__ vel, uint2* __restrict__ m16)
{
    int ix = threadIdx.x;
    int iy = blockIdx.x;
    int iz = blockIdx.y;
    int idx = (iz * DIM + iy) * DIM + ix;
    int b = idx * 3;
    const float s = 1.0f / 64.0f;
    m16[idx] = pack_h16(vel[b] * s, vel[b + 1] * s, vel[b + 2] * s);
}

extern "C" void kernel_launch(void* const* d_in, const int* in_sizes, int n_in,
                              void* d_out, int out_size)
{
    const float* vel = (const float*)d_in[0];  // [1,160,160,160,3] f32
    // d_in[1] = identity grid (analytic). d_in[2] = n (= 6).
    float* out = (float*)d_out;

    uint2 *hA, *hB;
    float *sx, *sy, *sz;
    cudaGetSymbolAddress((void**)&hA, g_h16A);
    cudaGetSymbolAddress((void**)&hB, g_h16B);
    cudaGetSymbolAddress((void**)&sx, g_vx);
    cudaGetSymbolAddress((void**)&sy, g_vy);
    cudaGetSymbolAddress((void**)&sz, g_vz);

    dim3 grid(DIM, DIM);
    dim3 block(DIM);

    mirror_kernel<<<grid, block>>>(vel, hA);

    // step 0: own from vel (prescaled), gather hA -> hB
    step_kernel<0><<<grid, block>>>(vel, hA, hB, nullptr, nullptr, nullptr, nullptr);
    // steps 1-3: fp16 carried, ping-pong
    step_kernel<1><<<grid, block>>>(nullptr, hB, hA, nullptr, nullptr, nullptr, nullptr);
    step_kernel<1><<<grid, block>>>(nullptr, hA, hB, nullptr, nullptr, nullptr, nullptr);
    step_kernel<1><<<grid, block>>>(nullptr, hB, hA, nullptr, nullptr, nullptr, nullptr);
    // step 4: also writes fp32 SoA for the final step's own-v term
    step_kernel<2><<<grid, block>>>(nullptr, hA, hB, sx, sy, sz, nullptr);
    // step 5: own from fp32 SoA, gather hB -> packed d_out
    step_kernel<3><<<grid, block>>>(nullptr, hB, nullptr, sx, sy, sz, out);
}